// round 2
// baseline (speedup 1.0000x reference)
#include <cuda_runtime.h>
#include <math.h>

// Problem constants
#define NTOT 262144   // B * NPG
#define HD   256      // hidden dim
#define BG   64       // graphs
#define NPGC 4096     // nodes per graph
#define C0C  256      // level-0 clusters
#define C1C  64       // level-1 clusters
#define KSPLIT 16     // K-splits for final GEMM

// Scratch (device globals: no allocation allowed)
__device__ float g_A0[(size_t)NTOT * C0C];        // 268 MB  [N, C0]
__device__ float g_f0[(size_t)BG * C0C * HD];     // 16.8 MB [B*C0, H]
__device__ float g_A1[(size_t)BG * C0C * C1C];    // 4.2 MB  [B*C0, C1]
__device__ float g_f1[(size_t)BG * C1C * HD];     // 4.2 MB  [B, C1*H]
__device__ float g_part[(size_t)KSPLIT * BG * HD];// 1 MB    [KS, 64, 256]

// ---------------------------------------------------------------------------
// Kernel 1: A0 = softmax(x @ W0 + b0)   [N,256] @ [256,256]
// Block: 256 threads, tile 64 rows x 256 cols (full width -> softmax in-block)
// ---------------------------------------------------------------------------
__global__ __launch_bounds__(256) void k1_assign0(const float* __restrict__ x,
                                                  const float* __restrict__ W0,
                                                  const float* __restrict__ b0) {
    __shared__ float xs[64][33];    // [row][k], padded
    __shared__ float ws[32][256];   // [k][col]
    const int tid = threadIdx.x;
    const int tx = tid & 15;        // col group
    const int ty = tid >> 4;        // row group (4 rows)
    const int row0 = blockIdx.x * 64;

    float acc[4][16];
#pragma unroll
    for (int i = 0; i < 4; i++)
#pragma unroll
        for (int j = 0; j < 16; j++) acc[i][j] = 0.f;

    for (int kb = 0; kb < HD; kb += 32) {
        // load x tile: 64 rows x 32 k
        {
            int r  = tid >> 2;
            int k4 = (tid & 3) * 8;
            const float4* src = (const float4*)(x + (size_t)(row0 + r) * HD + kb + k4);
            float4 v0 = src[0], v1 = src[1];
            xs[r][k4 + 0] = v0.x; xs[r][k4 + 1] = v0.y; xs[r][k4 + 2] = v0.z; xs[r][k4 + 3] = v0.w;
            xs[r][k4 + 4] = v1.x; xs[r][k4 + 5] = v1.y; xs[r][k4 + 6] = v1.z; xs[r][k4 + 7] = v1.w;
        }
        // load W0 tile: 32 k x 256 cols
#pragma unroll
        for (int i = 0; i < 8; i++) {
            int idx = tid + i * 256;          // 0..2047 float4s
            int k = idx >> 6;
            int c = (idx & 63) * 4;
            *(float4*)&ws[k][c] = *(const float4*)(W0 + (size_t)(kb + k) * C0C + c);
        }
        __syncthreads();
#pragma unroll
        for (int k = 0; k < 32; k++) {
            float a[4];
#pragma unroll
            for (int i = 0; i < 4; i++) a[i] = xs[ty * 4 + i][k];
            float b[16];
#pragma unroll
            for (int g = 0; g < 4; g++) {
                float4 bv = *(float4*)&ws[k][tx * 4 + g * 64];
                b[g * 4 + 0] = bv.x; b[g * 4 + 1] = bv.y; b[g * 4 + 2] = bv.z; b[g * 4 + 3] = bv.w;
            }
#pragma unroll
            for (int i = 0; i < 4; i++)
#pragma unroll
                for (int j = 0; j < 16; j++)
                    acc[i][j] = fmaf(a[i], b[j], acc[i][j]);
        }
        __syncthreads();
    }

    // bias
    float bias[16];
#pragma unroll
    for (int g = 0; g < 4; g++) {
        float4 bv = *(const float4*)(b0 + tx * 4 + g * 64);
        bias[g * 4 + 0] = bv.x; bias[g * 4 + 1] = bv.y; bias[g * 4 + 2] = bv.z; bias[g * 4 + 3] = bv.w;
    }

    // per-row softmax: rows of a given ty are reduced across the 16 tx lanes
#pragma unroll
    for (int i = 0; i < 4; i++) {
        float mx = -3.4e38f;
#pragma unroll
        for (int j = 0; j < 16; j++) { acc[i][j] += bias[j]; mx = fmaxf(mx, acc[i][j]); }
#pragma unroll
        for (int off = 8; off; off >>= 1)
            mx = fmaxf(mx, __shfl_xor_sync(0xffffffffu, mx, off, 16));
        float s = 0.f;
#pragma unroll
        for (int j = 0; j < 16; j++) { acc[i][j] = __expf(acc[i][j] - mx); s += acc[i][j]; }
#pragma unroll
        for (int off = 8; off; off >>= 1)
            s += __shfl_xor_sync(0xffffffffu, s, off, 16);
        float inv = 1.0f / s;
        size_t row = (size_t)(row0 + ty * 4 + i);
#pragma unroll
        for (int g = 0; g < 4; g++) {
            float4 o = make_float4(acc[i][g * 4 + 0] * inv, acc[i][g * 4 + 1] * inv,
                                   acc[i][g * 4 + 2] * inv, acc[i][g * 4 + 3] * inv);
            *(float4*)(g_A0 + row * C0C + tx * 4 + g * 64) = o;
        }
    }
}

// ---------------------------------------------------------------------------
// Kernel 2: per-graph f0 = A0^T @ x : [4096,256]^T x [4096,256] -> [256,256]
// 128x128 block tile, 8x8 per thread, K chunks of 16.  grid (2,2,64)
// ---------------------------------------------------------------------------
__global__ __launch_bounds__(256) void k2_pool0(const float* __restrict__ x) {
    __shared__ float As[16][128];   // [k][m]
    __shared__ float Xs[16][128];   // [k][n]
    const int g  = blockIdx.z;
    const int m0 = blockIdx.y * 128;
    const int n0 = blockIdx.x * 128;
    const int tid = threadIdx.x;
    const int tx = tid & 15, ty = tid >> 4;

    float acc[8][8];
#pragma unroll
    for (int i = 0; i < 8; i++)
#pragma unroll
        for (int j = 0; j < 8; j++) acc[i][j] = 0.f;

    const float* A0p = g_A0 + (size_t)g * NPGC * C0C;
    const float* xp  = x    + (size_t)g * NPGC * HD;

    for (int kb = 0; kb < NPGC; kb += 16) {
#pragma unroll
        for (int i = 0; i < 2; i++) {
            int idx = tid + i * 256;          // 0..511 float4s
            int k = idx >> 5;
            int c = (idx & 31) * 4;
            *(float4*)&As[k][c] = *(const float4*)(A0p + (size_t)(kb + k) * C0C + m0 + c);
            *(float4*)&Xs[k][c] = *(const float4*)(xp  + (size_t)(kb + k) * HD  + n0 + c);
        }
        __syncthreads();
#pragma unroll
        for (int k = 0; k < 16; k++) {
            float a[8], b[8];
            *(float4*)&a[0] = *(float4*)&As[k][ty * 4];
            *(float4*)&a[4] = *(float4*)&As[k][ty * 4 + 64];
            *(float4*)&b[0] = *(float4*)&Xs[k][tx * 4];
            *(float4*)&b[4] = *(float4*)&Xs[k][tx * 4 + 64];
#pragma unroll
            for (int i = 0; i < 8; i++)
#pragma unroll
                for (int j = 0; j < 8; j++)
                    acc[i][j] = fmaf(a[i], b[j], acc[i][j]);
        }
        __syncthreads();
    }

    float* f0p = g_f0 + (size_t)g * C0C * HD;
#pragma unroll
    for (int gm = 0; gm < 2; gm++)
#pragma unroll
        for (int ii = 0; ii < 4; ii++) {
            int m = m0 + ty * 4 + ii + gm * 64;
#pragma unroll
            for (int gn = 0; gn < 2; gn++) {
                float4 o = make_float4(acc[gm * 4 + ii][gn * 4 + 0], acc[gm * 4 + ii][gn * 4 + 1],
                                       acc[gm * 4 + ii][gn * 4 + 2], acc[gm * 4 + ii][gn * 4 + 3]);
                *(float4*)(f0p + (size_t)m * HD + n0 + tx * 4 + gn * 64) = o;
            }
        }
}

// ---------------------------------------------------------------------------
// Kernel 3: A1 = softmax(f0 @ W1 + b1)   [16384,256] @ [256,64]
// One warp per row; lane handles cols lane, lane+32.
// ---------------------------------------------------------------------------
__global__ __launch_bounds__(256) void k3_assign1(const float* __restrict__ W1,
                                                  const float* __restrict__ b1) {
    int gw = (blockIdx.x * blockDim.x + threadIdx.x) >> 5;
    int lane = threadIdx.x & 31;
    if (gw >= BG * C0C) return;
    const float* xr = g_f0 + (size_t)gw * HD;
    float acc0 = 0.f, acc1 = 0.f;
#pragma unroll 8
    for (int k = 0; k < HD; k++) {
        float xv = __ldg(xr + k);
        acc0 = fmaf(xv, __ldg(W1 + (size_t)k * C1C + lane),      acc0);
        acc1 = fmaf(xv, __ldg(W1 + (size_t)k * C1C + lane + 32), acc1);
    }
    acc0 += __ldg(b1 + lane);
    acc1 += __ldg(b1 + lane + 32);
    float mx = fmaxf(acc0, acc1);
#pragma unroll
    for (int off = 16; off; off >>= 1)
        mx = fmaxf(mx, __shfl_xor_sync(0xffffffffu, mx, off));
    acc0 = __expf(acc0 - mx);
    acc1 = __expf(acc1 - mx);
    float s = acc0 + acc1;
#pragma unroll
    for (int off = 16; off; off >>= 1)
        s += __shfl_xor_sync(0xffffffffu, s, off);
    float inv = 1.0f / s;
    g_A1[(size_t)gw * C1C + lane]      = acc0 * inv;
    g_A1[(size_t)gw * C1C + lane + 32] = acc1 * inv;
}

// ---------------------------------------------------------------------------
// Kernel 4: per-graph f1 = A1^T @ f0 : [256,64]^T x [256,256] -> [64,256]
// Block tile 64m x 128n, grid (2,64)
// ---------------------------------------------------------------------------
__global__ __launch_bounds__(256) void k4_pool1() {
    __shared__ float As[32][64];     // [k][m]
    __shared__ float Fs[32][128];    // [k][n]
    const int g  = blockIdx.y;
    const int n0 = blockIdx.x * 128;
    const int tid = threadIdx.x;
    const int tx = tid & 15, ty = tid >> 4;

    float acc[4][8];
#pragma unroll
    for (int i = 0; i < 4; i++)
#pragma unroll
        for (int j = 0; j < 8; j++) acc[i][j] = 0.f;

    const float* A1p = g_A1 + (size_t)g * C0C * C1C;
    const float* f0p = g_f0 + (size_t)g * C0C * HD;

    for (int kb = 0; kb < C0C; kb += 32) {
#pragma unroll
        for (int i = 0; i < 2; i++) {
            int idx = tid + i * 256;          // 0..511 float4s (32x64)
            int k = idx >> 4;
            int m = (idx & 15) * 4;
            *(float4*)&As[k][m] = *(const float4*)(A1p + (size_t)(kb + k) * C1C + m);
        }
#pragma unroll
        for (int i = 0; i < 4; i++) {
            int idx = tid + i * 256;          // 0..1023 float4s (32x128)
            int k = idx >> 5;
            int c = (idx & 31) * 4;
            *(float4*)&Fs[k][c] = *(const float4*)(f0p + (size_t)(kb + k) * HD + n0 + c);
        }
        __syncthreads();
#pragma unroll
        for (int k = 0; k < 32; k++) {
            float a[4], b[8];
            *(float4*)&a[0] = *(float4*)&As[k][ty * 4];
            *(float4*)&b[0] = *(float4*)&Fs[k][tx * 4];
            *(float4*)&b[4] = *(float4*)&Fs[k][tx * 4 + 64];
#pragma unroll
            for (int i = 0; i < 4; i++)
#pragma unroll
                for (int j = 0; j < 8; j++)
                    acc[i][j] = fmaf(a[i], b[j], acc[i][j]);
        }
        __syncthreads();
    }

    float* f1p = g_f1 + (size_t)g * C1C * HD;
#pragma unroll
    for (int ii = 0; ii < 4; ii++) {
        int m = ty * 4 + ii;
#pragma unroll
        for (int gn = 0; gn < 2; gn++) {
            float4 o = make_float4(acc[ii][gn * 4 + 0], acc[ii][gn * 4 + 1],
                                   acc[ii][gn * 4 + 2], acc[ii][gn * 4 + 3]);
            *(float4*)(f1p + (size_t)m * HD + n0 + tx * 4 + gn * 64) = o;
        }
    }
}

// ---------------------------------------------------------------------------
// Kernel 5: partial final GEMM  part[ks] += f1[64,16384-slice] @ Wf[slice,32-cols]
// grid (8 n-tiles, 16 k-splits); block tile 64m x 32n, K chunk 32
// ---------------------------------------------------------------------------
__global__ __launch_bounds__(256) void k5_final_part(const float* __restrict__ Wf) {
    __shared__ float Fs[64][33];    // [m][kk] padded
    __shared__ float Ws[32][32];    // [kk][n]
    const int n0 = blockIdx.x * 32;
    const int ks = blockIdx.y;
    const int tid = threadIdx.x;
    const int tx = tid & 31;        // n
    const int ty = tid >> 5;        // 0..7 (8 m-rows each)

    float acc[8];
#pragma unroll
    for (int i = 0; i < 8; i++) acc[i] = 0.f;

    const int kbeg = ks * ((BG * C1C * HD / BG) / KSPLIT); // 16384/16 = 1024
    for (int kb = kbeg; kb < kbeg + 1024; kb += 32) {
#pragma unroll
        for (int i = 0; i < 2; i++) {
            int idx = tid + i * 256;          // 0..511 float4s (64x32)
            int m = idx >> 3;
            int k = (idx & 7) * 4;
            float4 v = *(const float4*)(g_f1 + (size_t)m * (C1C * HD) + kb + k);
            Fs[m][k + 0] = v.x; Fs[m][k + 1] = v.y; Fs[m][k + 2] = v.z; Fs[m][k + 3] = v.w;
        }
        {
            int k = tid >> 3;
            int n = (tid & 7) * 4;
            *(float4*)&Ws[k][n] = *(const float4*)(Wf + (size_t)(kb + k) * HD + n0 + n);
        }
        __syncthreads();
#pragma unroll
        for (int kk = 0; kk < 32; kk++) {
            float b = Ws[kk][tx];
#pragma unroll
            for (int i = 0; i < 8; i++)
                acc[i] = fmaf(Fs[ty * 8 + i][kk], b, acc[i]);
        }
        __syncthreads();
    }
#pragma unroll
    for (int i = 0; i < 8; i++)
        g_part[(size_t)(ks * BG + ty * 8 + i) * HD + n0 + tx] = acc[i];
}

// ---------------------------------------------------------------------------
// Kernel 6: out = relu(sum_ks part + bf)
// ---------------------------------------------------------------------------
__global__ __launch_bounds__(256) void k6_reduce(const float* __restrict__ bf,
                                                 float* __restrict__ out) {
    int idx = blockIdx.x * 256 + threadIdx.x;   // < 64*256
    float s = __ldg(bf + (idx & 255));
#pragma unroll
    for (int ks = 0; ks < KSPLIT; ks++)
        s += g_part[(size_t)ks * (BG * HD) + idx];
    out[idx] = fmaxf(s, 0.f);
}

// ---------------------------------------------------------------------------
extern "C" void kernel_launch(void* const* d_in, const int* in_sizes, int n_in,
                              void* d_out, int out_size) {
    const float* x  = (const float*)d_in[0];
    // d_in[1] edge_index (int64, unused), d_in[2] batch (int64, unused)
    const float* W0 = (const float*)d_in[3];
    const float* b0 = (const float*)d_in[4];
    const float* W1 = (const float*)d_in[5];
    const float* b1 = (const float*)d_in[6];
    const float* Wf = (const float*)d_in[7];
    const float* bf = (const float*)d_in[8];
    float* out = (float*)d_out;

    k1_assign0<<<NTOT / 64, 256>>>(x, W0, b0);
    k2_pool0<<<dim3(2, 2, BG), 256>>>(x);
    k3_assign1<<<(BG * C0C * 32) / 256, 256>>>(W1, b1);
    k4_pool1<<<dim3(2, BG), 256>>>();
    k5_final_part<<<dim3(8, KSPLIT), 256>>>(Wf);
    k6_reduce<<<(BG * HD) / 256, 256>>>(bf, out);
}

// round 3
// speedup vs baseline: 1.0026x; 1.0026x over previous
#include <cuda_runtime.h>
#include <math.h>

// Problem constants
#define NTOT 262144   // B * NPG
#define HD   256      // hidden dim
#define BG   64       // graphs
#define NPGC 4096     // nodes per graph
#define C0C  256      // level-0 clusters
#define C1C  64       // level-1 clusters
#define KSPLIT 16     // K-splits for final GEMM

// Scratch (device globals: no allocation allowed)
__device__ float g_A0[(size_t)NTOT * C0C];        // 268 MB  [N, C0]
__device__ float g_f0[(size_t)BG * C0C * HD];     // 16.8 MB [B*C0, H]
__device__ float g_A1[(size_t)BG * C0C * C1C];    // 4.2 MB  [B*C0, C1]
__device__ float g_f1[(size_t)BG * C1C * HD];     // 4.2 MB  [B, C1*H]
__device__ float g_part[(size_t)KSPLIT * BG * HD];// 1 MB    [KS, 64, 256]

// ---------------------------------------------------------------------------
// Kernel 1: A0 = softmax(x @ W0 + b0)   [N,256] @ [256,256]
// Block: 256 threads, tile 64 rows x 256 cols (full width -> softmax in-block)
// ---------------------------------------------------------------------------
__global__ __launch_bounds__(256) void k1_assign0(const float* __restrict__ x,
                                                  const float* __restrict__ W0,
                                                  const float* __restrict__ b0) {
    __shared__ float xs[64][33];    // [row][k], padded
    __shared__ float ws[32][256];   // [k][col]
    const int tid = threadIdx.x;
    const int tx = tid & 15;        // col group
    const int ty = tid >> 4;        // row group (4 rows)
    const int row0 = blockIdx.x * 64;

    float acc[4][16];
#pragma unroll
    for (int i = 0; i < 4; i++)
#pragma unroll
        for (int j = 0; j < 16; j++) acc[i][j] = 0.f;

    for (int kb = 0; kb < HD; kb += 32) {
        // load x tile: 64 rows x 32 k
        {
            int r  = tid >> 2;
            int k4 = (tid & 3) * 8;
            const float4* src = (const float4*)(x + (size_t)(row0 + r) * HD + kb + k4);
            float4 v0 = src[0], v1 = src[1];
            xs[r][k4 + 0] = v0.x; xs[r][k4 + 1] = v0.y; xs[r][k4 + 2] = v0.z; xs[r][k4 + 3] = v0.w;
            xs[r][k4 + 4] = v1.x; xs[r][k4 + 5] = v1.y; xs[r][k4 + 6] = v1.z; xs[r][k4 + 7] = v1.w;
        }
        // load W0 tile: 32 k x 256 cols
#pragma unroll
        for (int i = 0; i < 8; i++) {
            int idx = tid + i * 256;          // 0..2047 float4s
            int k = idx >> 6;
            int c = (idx & 63) * 4;
            *(float4*)&ws[k][c] = *(const float4*)(W0 + (size_t)(kb + k) * C0C + c);
        }
        __syncthreads();
#pragma unroll
        for (int k = 0; k < 32; k++) {
            float a[4];
#pragma unroll
            for (int i = 0; i < 4; i++) a[i] = xs[ty * 4 + i][k];
            float b[16];
#pragma unroll
            for (int g = 0; g < 4; g++) {
                float4 bv = *(float4*)&ws[k][tx * 4 + g * 64];
                b[g * 4 + 0] = bv.x; b[g * 4 + 1] = bv.y; b[g * 4 + 2] = bv.z; b[g * 4 + 3] = bv.w;
            }
#pragma unroll
            for (int i = 0; i < 4; i++)
#pragma unroll
                for (int j = 0; j < 16; j++)
                    acc[i][j] = fmaf(a[i], b[j], acc[i][j]);
        }
        __syncthreads();
    }

    // bias
    float bias[16];
#pragma unroll
    for (int g = 0; g < 4; g++) {
        float4 bv = *(const float4*)(b0 + tx * 4 + g * 64);
        bias[g * 4 + 0] = bv.x; bias[g * 4 + 1] = bv.y; bias[g * 4 + 2] = bv.z; bias[g * 4 + 3] = bv.w;
    }

    // per-row softmax: rows of a given ty are reduced across the 16 tx lanes
#pragma unroll
    for (int i = 0; i < 4; i++) {
        float mx = -3.4e38f;
#pragma unroll
        for (int j = 0; j < 16; j++) { acc[i][j] += bias[j]; mx = fmaxf(mx, acc[i][j]); }
#pragma unroll
        for (int off = 8; off; off >>= 1)
            mx = fmaxf(mx, __shfl_xor_sync(0xffffffffu, mx, off, 16));
        float s = 0.f;
#pragma unroll
        for (int j = 0; j < 16; j++) { acc[i][j] = __expf(acc[i][j] - mx); s += acc[i][j]; }
#pragma unroll
        for (int off = 8; off; off >>= 1)
            s += __shfl_xor_sync(0xffffffffu, s, off, 16);
        float inv = 1.0f / s;
        size_t row = (size_t)(row0 + ty * 4 + i);
#pragma unroll
        for (int g = 0; g < 4; g++) {
            float4 o = make_float4(acc[i][g * 4 + 0] * inv, acc[i][g * 4 + 1] * inv,
                                   acc[i][g * 4 + 2] * inv, acc[i][g * 4 + 3] * inv);
            *(float4*)(g_A0 + row * C0C + tx * 4 + g * 64) = o;
        }
    }
}

// ---------------------------------------------------------------------------
// Kernel 2: per-graph f0 = A0^T @ x : [4096,256]^T x [4096,256] -> [256,256]
// 128x128 block tile, 8x8 per thread, K chunks of 16.  grid (2,2,64)
// ---------------------------------------------------------------------------
__global__ __launch_bounds__(256) void k2_pool0(const float* __restrict__ x) {
    __shared__ float As[16][128];   // [k][m]
    __shared__ float Xs[16][128];   // [k][n]
    const int g  = blockIdx.z;
    const int m0 = blockIdx.y * 128;
    const int n0 = blockIdx.x * 128;
    const int tid = threadIdx.x;
    const int tx = tid & 15, ty = tid >> 4;

    float acc[8][8];
#pragma unroll
    for (int i = 0; i < 8; i++)
#pragma unroll
        for (int j = 0; j < 8; j++) acc[i][j] = 0.f;

    const float* A0p = g_A0 + (size_t)g * NPGC * C0C;
    const float* xp  = x    + (size_t)g * NPGC * HD;

    for (int kb = 0; kb < NPGC; kb += 16) {
#pragma unroll
        for (int i = 0; i < 2; i++) {
            int idx = tid + i * 256;          // 0..511 float4s
            int k = idx >> 5;
            int c = (idx & 31) * 4;
            *(float4*)&As[k][c] = *(const float4*)(A0p + (size_t)(kb + k) * C0C + m0 + c);
            *(float4*)&Xs[k][c] = *(const float4*)(xp  + (size_t)(kb + k) * HD  + n0 + c);
        }
        __syncthreads();
#pragma unroll
        for (int k = 0; k < 16; k++) {
            float a[8], b[8];
            *(float4*)&a[0] = *(float4*)&As[k][ty * 4];
            *(float4*)&a[4] = *(float4*)&As[k][ty * 4 + 64];
            *(float4*)&b[0] = *(float4*)&Xs[k][tx * 4];
            *(float4*)&b[4] = *(float4*)&Xs[k][tx * 4 + 64];
#pragma unroll
            for (int i = 0; i < 8; i++)
#pragma unroll
                for (int j = 0; j < 8; j++)
                    acc[i][j] = fmaf(a[i], b[j], acc[i][j]);
        }
        __syncthreads();
    }

    float* f0p = g_f0 + (size_t)g * C0C * HD;
#pragma unroll
    for (int gm = 0; gm < 2; gm++)
#pragma unroll
        for (int ii = 0; ii < 4; ii++) {
            int m = m0 + ty * 4 + ii + gm * 64;
#pragma unroll
            for (int gn = 0; gn < 2; gn++) {
                float4 o = make_float4(acc[gm * 4 + ii][gn * 4 + 0], acc[gm * 4 + ii][gn * 4 + 1],
                                       acc[gm * 4 + ii][gn * 4 + 2], acc[gm * 4 + ii][gn * 4 + 3]);
                *(float4*)(f0p + (size_t)m * HD + n0 + tx * 4 + gn * 64) = o;
            }
        }
}

// ---------------------------------------------------------------------------
// Kernel 3: A1 = softmax(f0 @ W1 + b1)   [16384,256] @ [256,64]
// One warp per row; lane handles cols lane, lane+32.
// ---------------------------------------------------------------------------
__global__ __launch_bounds__(256) void k3_assign1(const float* __restrict__ W1,
                                                  const float* __restrict__ b1) {
    int gw = (blockIdx.x * blockDim.x + threadIdx.x) >> 5;
    int lane = threadIdx.x & 31;
    if (gw >= BG * C0C) return;
    const float* xr = g_f0 + (size_t)gw * HD;
    float acc0 = 0.f, acc1 = 0.f;
#pragma unroll 8
    for (int k = 0; k < HD; k++) {
        float xv = __ldg(xr + k);
        acc0 = fmaf(xv, __ldg(W1 + (size_t)k * C1C + lane),      acc0);
        acc1 = fmaf(xv, __ldg(W1 + (size_t)k * C1C + lane + 32), acc1);
    }
    acc0 += __ldg(b1 + lane);
    acc1 += __ldg(b1 + lane + 32);
    float mx = fmaxf(acc0, acc1);
#pragma unroll
    for (int off = 16; off; off >>= 1)
        mx = fmaxf(mx, __shfl_xor_sync(0xffffffffu, mx, off));
    acc0 = __expf(acc0 - mx);
    acc1 = __expf(acc1 - mx);
    float s = acc0 + acc1;
#pragma unroll
    for (int off = 16; off; off >>= 1)
        s += __shfl_xor_sync(0xffffffffu, s, off);
    float inv = 1.0f / s;
    g_A1[(size_t)gw * C1C + lane]      = acc0 * inv;
    g_A1[(size_t)gw * C1C + lane + 32] = acc1 * inv;
}

// ---------------------------------------------------------------------------
// Kernel 4: per-graph f1 = A1^T @ f0 : [256,64]^T x [256,256] -> [64,256]
// Block tile 64m x 128n, grid (2,64)
// ---------------------------------------------------------------------------
__global__ __launch_bounds__(256) void k4_pool1() {
    __shared__ float As[32][64];     // [k][m]
    __shared__ float Fs[32][128];    // [k][n]
    const int g  = blockIdx.y;
    const int n0 = blockIdx.x * 128;
    const int tid = threadIdx.x;
    const int tx = tid & 15, ty = tid >> 4;

    float acc[4][8];
#pragma unroll
    for (int i = 0; i < 4; i++)
#pragma unroll
        for (int j = 0; j < 8; j++) acc[i][j] = 0.f;

    const float* A1p = g_A1 + (size_t)g * C0C * C1C;
    const float* f0p = g_f0 + (size_t)g * C0C * HD;

    for (int kb = 0; kb < C0C; kb += 32) {
#pragma unroll
        for (int i = 0; i < 2; i++) {
            int idx = tid + i * 256;          // 0..511 float4s (32x64)
            int k = idx >> 4;
            int m = (idx & 15) * 4;
            *(float4*)&As[k][m] = *(const float4*)(A1p + (size_t)(kb + k) * C1C + m);
        }
#pragma unroll
        for (int i = 0; i < 4; i++) {
            int idx = tid + i * 256;          // 0..1023 float4s (32x128)
            int k = idx >> 5;
            int c = (idx & 31) * 4;
            *(float4*)&Fs[k][c] = *(const float4*)(f0p + (size_t)(kb + k) * HD + n0 + c);
        }
        __syncthreads();
#pragma unroll
        for (int k = 0; k < 32; k++) {
            float a[4], b[8];
            *(float4*)&a[0] = *(float4*)&As[k][ty * 4];
            *(float4*)&b[0] = *(float4*)&Fs[k][tx * 4];
            *(float4*)&b[4] = *(float4*)&Fs[k][tx * 4 + 64];
#pragma unroll
            for (int i = 0; i < 4; i++)
#pragma unroll
                for (int j = 0; j < 8; j++)
                    acc[i][j] = fmaf(a[i], b[j], acc[i][j]);
        }
        __syncthreads();
    }

    float* f1p = g_f1 + (size_t)g * C1C * HD;
#pragma unroll
    for (int ii = 0; ii < 4; ii++) {
        int m = ty * 4 + ii;
#pragma unroll
        for (int gn = 0; gn < 2; gn++) {
            float4 o = make_float4(acc[ii][gn * 4 + 0], acc[ii][gn * 4 + 1],
                                   acc[ii][gn * 4 + 2], acc[ii][gn * 4 + 3]);
            *(float4*)(f1p + (size_t)m * HD + n0 + tx * 4 + gn * 64) = o;
        }
    }
}

// ---------------------------------------------------------------------------
// Kernel 5: partial final GEMM  part[ks] += f1[64,16384-slice] @ Wf[slice,32-cols]
// grid (8 n-tiles, 16 k-splits); block tile 64m x 32n, K chunk 32
// ---------------------------------------------------------------------------
__global__ __launch_bounds__(256) void k5_final_part(const float* __restrict__ Wf) {
    __shared__ float Fs[64][33];    // [m][kk] padded
    __shared__ float Ws[32][32];    // [kk][n]
    const int n0 = blockIdx.x * 32;
    const int ks = blockIdx.y;
    const int tid = threadIdx.x;
    const int tx = tid & 31;        // n
    const int ty = tid >> 5;        // 0..7 (8 m-rows each)

    float acc[8];
#pragma unroll
    for (int i = 0; i < 8; i++) acc[i] = 0.f;

    const int kbeg = ks * ((BG * C1C * HD / BG) / KSPLIT); // 16384/16 = 1024
    for (int kb = kbeg; kb < kbeg + 1024; kb += 32) {
#pragma unroll
        for (int i = 0; i < 2; i++) {
            int idx = tid + i * 256;          // 0..511 float4s (64x32)
            int m = idx >> 3;
            int k = (idx & 7) * 4;
            float4 v = *(const float4*)(g_f1 + (size_t)m * (C1C * HD) + kb + k);
            Fs[m][k + 0] = v.x; Fs[m][k + 1] = v.y; Fs[m][k + 2] = v.z; Fs[m][k + 3] = v.w;
        }
        {
            int k = tid >> 3;
            int n = (tid & 7) * 4;
            *(float4*)&Ws[k][n] = *(const float4*)(Wf + (size_t)(kb + k) * HD + n0 + n);
        }
        __syncthreads();
#pragma unroll
        for (int kk = 0; kk < 32; kk++) {
            float b = Ws[kk][tx];
#pragma unroll
            for (int i = 0; i < 8; i++)
                acc[i] = fmaf(Fs[ty * 8 + i][kk], b, acc[i]);
        }
        __syncthreads();
    }
#pragma unroll
    for (int i = 0; i < 8; i++)
        g_part[(size_t)(ks * BG + ty * 8 + i) * HD + n0 + tx] = acc[i];
}

// ---------------------------------------------------------------------------
// Kernel 6: out = relu(sum_ks part + bf)
// ---------------------------------------------------------------------------
__global__ __launch_bounds__(256) void k6_reduce(const float* __restrict__ bf,
                                                 float* __restrict__ out) {
    int idx = blockIdx.x * 256 + threadIdx.x;   // < 64*256
    float s = __ldg(bf + (idx & 255));
#pragma unroll
    for (int ks = 0; ks < KSPLIT; ks++)
        s += g_part[(size_t)ks * (BG * HD) + idx];
    out[idx] = fmaxf(s, 0.f);
}

// ---------------------------------------------------------------------------
extern "C" void kernel_launch(void* const* d_in, const int* in_sizes, int n_in,
                              void* d_out, int out_size) {
    const float* x  = (const float*)d_in[0];
    // d_in[1] edge_index (int64, unused), d_in[2] batch (int64, unused)
    const float* W0 = (const float*)d_in[3];
    const float* b0 = (const float*)d_in[4];
    const float* W1 = (const float*)d_in[5];
    const float* b1 = (const float*)d_in[6];
    const float* Wf = (const float*)d_in[7];
    const float* bf = (const float*)d_in[8];
    float* out = (float*)d_out;

    k1_assign0<<<NTOT / 64, 256>>>(x, W0, b0);
    k2_pool0<<<dim3(2, 2, BG), 256>>>(x);
    k3_assign1<<<(BG * C0C * 32) / 256, 256>>>(W1, b1);
    k4_pool1<<<dim3(2, BG), 256>>>();
    k5_final_part<<<dim3(8, KSPLIT), 256>>>(Wf);
    k6_reduce<<<(BG * HD) / 256, 256>>>(bf, out);
}

// round 6
// speedup vs baseline: 1.6640x; 1.6596x over previous
#include <cuda_runtime.h>
#include <cuda_bf16.h>

#define HD 256
#define BG 64
#define NPGC 4096
#define C0C 256
#define C1C 64
#define NTOT (BG*NPGC)
#define KSPLIT 16

__device__ unsigned g_A0P[(size_t)BG*C0C*NPGC];  // packed bf16 hi|lo<<16, [g][c][n]
__device__ unsigned g_W0P[C0C*HD];               // W0^T packed [c][k]
__device__ float g_f0[(size_t)BG*C0C*HD];
__device__ float g_A1[(size_t)BG*C0C*C1C];
__device__ float g_f1[(size_t)BG*C1C*HD];
__device__ float g_part[(size_t)KSPLIT*BG*HD];

__device__ __forceinline__ unsigned pack1(float v){
    __nv_bfloat16 h = __float2bfloat16(v);
    __nv_bfloat16 lo = __float2bfloat16(v - __bfloat162float(h));
    return (unsigned)__bfloat16_as_ushort(h) | ((unsigned)__bfloat16_as_ushort(lo)<<16);
}
__device__ __forceinline__ uint4 pack4(float4 v){
    return make_uint4(pack1(v.x), pack1(v.y), pack1(v.z), pack1(v.w));
}
__device__ __forceinline__ void mma16816(float* c, const unsigned* a, const unsigned* b){
    asm volatile("mma.sync.aligned.m16n8k16.row.col.f32.bf16.bf16.f32 "
        "{%0,%1,%2,%3}, {%4,%5,%6,%7}, {%8,%9}, {%0,%1,%2,%3};"
        : "+f"(c[0]),"+f"(c[1]),"+f"(c[2]),"+f"(c[3])
        : "r"(a[0]),"r"(a[1]),"r"(a[2]),"r"(a[3]), "r"(b[0]),"r"(b[1]));
}

// pack W0^T: g_W0P[c][k] = split(W0[k][c])
__global__ void kW(const float* __restrict__ W0){
    int i = blockIdx.x*256 + threadIdx.x;    // 65536
    int k = i>>8, c = i&255;
    g_W0P[c*HD + k] = pack1(W0[(size_t)k*C0C + c]);
}

// =========================================================================
// k1m: A0 = softmax(x@W0 + b0), HMMA split-bf16, 128 rows/CTA, 256 thr.
// Writes A0 transposed+packed to g_A0P.
// =========================================================================
#define SX_STR 136   // 128 k + pad (stride%32==8 -> conflict-free frag loads)
#define SW_STR 136
#define K1_SMEM (2048 + 128*SX_STR*4 + 256*SW_STR*4)   // 210944
__global__ __launch_bounds__(256,1) void k1m(const float* __restrict__ x,
                                             const float* __restrict__ b0){
    extern __shared__ __align__(16) unsigned sm[];
    float* sums = (float*)sm;                 // [128][2]
    float* b0s  = (float*)(sm + 256);         // [256]
    unsigned* sX = sm + 512;                  // [128][136]
    unsigned* sW = sm + 512 + 128*SX_STR;     // [256][136]
    unsigned* buf = sm + 512;                 // epilogue staging [256][132]
    const int tid = threadIdx.x, l = tid&31, wid = tid>>5;
    const int wm = wid&3, wn = wid>>2;        // 4 m-warps x 2 n-warps
    const int row0 = blockIdx.x*128;

    b0s[tid] = b0[tid];
    float acc[2][16][4];
#pragma unroll
    for(int t=0;t<2;t++)
#pragma unroll
        for(int j=0;j<16;j++)
#pragma unroll
            for(int q=0;q<4;q++) acc[t][j][q]=0.f;

    for(int kc=0;kc<2;kc++){
        // load + split x chunk [128 r][128 k]
#pragma unroll
        for(int i=0;i<16;i++){
            int idx = tid + i*256, r = idx>>5, q = idx&31;
            float4 v = *(const float4*)(x + (size_t)(row0+r)*HD + kc*128 + q*4);
            *(uint4*)(sX + r*SX_STR + q*4) = pack4(v);
        }
        // copy W0P chunk [256 c][128 k]
#pragma unroll
        for(int i=0;i<32;i++){
            int idx = tid + i*256, c = idx>>5, q = idx&31;
            *(uint4*)(sW + c*SW_STR + q*4) = *(const uint4*)(g_W0P + c*HD + kc*128 + q*4);
        }
        __syncthreads();
        for(int k16=0;k16<8;k16++){
            int kb = k16*16;
            unsigned ah[2][4], al[2][4];
#pragma unroll
            for(int t=0;t<2;t++){
                int ra = (wm*32 + t*16 + (l>>2))*SX_STR + kb + (l&3)*2;
                uint2 p0 = *(uint2*)(sX+ra),            p1 = *(uint2*)(sX+ra+8*SX_STR);
                uint2 p2 = *(uint2*)(sX+ra+8),          p3 = *(uint2*)(sX+ra+8*SX_STR+8);
                ah[t][0]=__byte_perm(p0.x,p0.y,0x5410); al[t][0]=__byte_perm(p0.x,p0.y,0x7632);
                ah[t][1]=__byte_perm(p1.x,p1.y,0x5410); al[t][1]=__byte_perm(p1.x,p1.y,0x7632);
                ah[t][2]=__byte_perm(p2.x,p2.y,0x5410); al[t][2]=__byte_perm(p2.x,p2.y,0x7632);
                ah[t][3]=__byte_perm(p3.x,p3.y,0x5410); al[t][3]=__byte_perm(p3.x,p3.y,0x7632);
            }
#pragma unroll
            for(int j=0;j<16;j++){
                int rb = (wn*128 + j*8 + (l>>2))*SW_STR + kb + (l&3)*2;
                uint2 q0 = *(uint2*)(sW+rb), q1 = *(uint2*)(sW+rb+8);
                unsigned bh[2], bl[2];
                bh[0]=__byte_perm(q0.x,q0.y,0x5410); bl[0]=__byte_perm(q0.x,q0.y,0x7632);
                bh[1]=__byte_perm(q1.x,q1.y,0x5410); bl[1]=__byte_perm(q1.x,q1.y,0x7632);
#pragma unroll
                for(int t=0;t<2;t++){
                    mma16816(acc[t][j], ah[t], bh);
                    mma16816(acc[t][j], ah[t], bl);
                    mma16816(acc[t][j], al[t], bh);
                }
            }
        }
        __syncthreads();
    }

    // epilogue: bias + exp + row-sum softmax
    float rs[2][2] = {{0.f,0.f},{0.f,0.f}};
#pragma unroll
    for(int t=0;t<2;t++)
#pragma unroll
        for(int j=0;j<16;j++){
            int col = wn*128 + j*8 + (l&3)*2;
            float e0=__expf(acc[t][j][0]+b0s[col]),   e1=__expf(acc[t][j][1]+b0s[col+1]);
            float e2=__expf(acc[t][j][2]+b0s[col]),   e3=__expf(acc[t][j][3]+b0s[col+1]);
            acc[t][j][0]=e0; acc[t][j][1]=e1; acc[t][j][2]=e2; acc[t][j][3]=e3;
            rs[t][0]+=e0+e1; rs[t][1]+=e2+e3;
        }
#pragma unroll
    for(int t=0;t<2;t++)
#pragma unroll
        for(int h=0;h<2;h++){
            float s = rs[t][h];
            s += __shfl_xor_sync(~0u,s,1); s += __shfl_xor_sync(~0u,s,2);
            rs[t][h]=s;
        }
    if((l&3)==0){
#pragma unroll
        for(int t=0;t<2;t++)
#pragma unroll
            for(int h=0;h<2;h++)
                sums[(wm*32+t*16+(l>>2)+8*h)*2 + wn] = rs[t][h];
    }
    __syncthreads();
    float inv[2][2];
#pragma unroll
    for(int t=0;t<2;t++)
#pragma unroll
        for(int h=0;h<2;h++){
            int r = wm*32+t*16+(l>>2)+8*h;
            inv[t][h] = 1.0f/(sums[r*2]+sums[r*2+1]);
        }
    // pack + transpose-stage into buf [col][row] (stride 132 -> conflict-free)
#pragma unroll
    for(int t=0;t<2;t++)
#pragma unroll
        for(int j=0;j<16;j++){
            int col = wn*128 + j*8 + (l&3)*2;
            int r0 = wm*32 + t*16 + (l>>2), r1 = r0+8;
            buf[col*132 + r0]     = pack1(acc[t][j][0]*inv[t][0]);
            buf[(col+1)*132 + r0] = pack1(acc[t][j][1]*inv[t][0]);
            buf[col*132 + r1]     = pack1(acc[t][j][2]*inv[t][1]);
            buf[(col+1)*132 + r1] = pack1(acc[t][j][3]*inv[t][1]);
        }
    __syncthreads();
    // coalesced transposed store: warp w handles cols w*32..+31
    const int g = row0>>12, nl0 = row0&4095;
#pragma unroll
    for(int cc=0;cc<32;cc++){
        int c = wid*32 + cc;
        uint4 v = *(uint4*)(buf + c*132 + l*4);
        *(uint4*)(g_A0P + ((size_t)g*C0C + c)*NPGC + nl0 + l*4) = v;
    }
}

// =========================================================================
// k2m: f0 = A0^T @ x per graph. grid(2 m-halves, 64 graphs). M=128,N=256,K=4096
// =========================================================================
#define SA_STR 72
#define SB_STR 72
#define SF_STR 260   // multiple of 4: float4 stores stay 16B-aligned (257 faulted)
#define K2_SMEM (128*SA_STR*4 + 256*SB_STR*4 + 64*SF_STR*4)   // 177152
__global__ __launch_bounds__(256,1) void k2m(const float* __restrict__ x){
    extern __shared__ __align__(16) unsigned sm[];
    unsigned* sA = sm;                            // [128][72] packed A0
    unsigned* sB = sm + 128*SA_STR;               // [256 h][72 n] packed x^T
    float*   sF = (float*)(sm + 128*SA_STR + 256*SB_STR); // [64 n][260 h]
    const int tid = threadIdx.x, l = tid&31, wid = tid>>5;
    const int wm = wid&3, wn = wid>>2;
    const int m0 = blockIdx.x*128, g = blockIdx.y;
    const unsigned* Ap = g_A0P + (size_t)g*C0C*NPGC;
    const float* xp = x + (size_t)g*NPGC*HD;

    float acc[2][16][4];
#pragma unroll
    for(int t=0;t<2;t++)
#pragma unroll
        for(int j=0;j<16;j++)
#pragma unroll
            for(int q=0;q<4;q++) acc[t][j][q]=0.f;

    for(int kc=0;kc<64;kc++){
        // A chunk: [128 c][64 n] packed u32, straight copy
#pragma unroll
        for(int i=0;i<8;i++){
            int idx = tid + i*256, r = idx>>4, q = idx&15;
            *(uint4*)(sA + r*SA_STR + q*4) =
                *(const uint4*)(Ap + (size_t)(m0+r)*NPGC + kc*64 + q*4);
        }
        // x chunk -> sF [64 n][260 h] fp32 (coalesced)
#pragma unroll
        for(int i=0;i<16;i++){
            int idx = tid + i*256, n = idx>>6, h4 = idx&63;
            *(float4*)(sF + n*SF_STR + h4*4) =
                *(const float4*)(xp + (size_t)(kc*64+n)*HD + h4*4);
        }
        __syncthreads();
        // transpose + split: thread tid = h row of sB
        {
            int h = tid;
#pragma unroll
            for(int n4=0;n4<16;n4++){
                unsigned p0 = pack1(sF[(n4*4+0)*SF_STR + h]);
                unsigned p1 = pack1(sF[(n4*4+1)*SF_STR + h]);
                unsigned p2 = pack1(sF[(n4*4+2)*SF_STR + h]);
                unsigned p3 = pack1(sF[(n4*4+3)*SF_STR + h]);
                *(uint4*)(sB + h*SB_STR + n4*4) = make_uint4(p0,p1,p2,p3);
            }
        }
        __syncthreads();
        for(int k16=0;k16<4;k16++){
            int kb = k16*16;
            unsigned ah[2][4], al[2][4];
#pragma unroll
            for(int t=0;t<2;t++){
                int ra = (wm*32 + t*16 + (l>>2))*SA_STR + kb + (l&3)*2;
                uint2 p0 = *(uint2*)(sA+ra),   p1 = *(uint2*)(sA+ra+8*SA_STR);
                uint2 p2 = *(uint2*)(sA+ra+8), p3 = *(uint2*)(sA+ra+8*SA_STR+8);
                ah[t][0]=__byte_perm(p0.x,p0.y,0x5410); al[t][0]=__byte_perm(p0.x,p0.y,0x7632);
                ah[t][1]=__byte_perm(p1.x,p1.y,0x5410); al[t][1]=__byte_perm(p1.x,p1.y,0x7632);
                ah[t][2]=__byte_perm(p2.x,p2.y,0x5410); al[t][2]=__byte_perm(p2.x,p2.y,0x7632);
                ah[t][3]=__byte_perm(p3.x,p3.y,0x5410); al[t][3]=__byte_perm(p3.x,p3.y,0x7632);
            }
#pragma unroll
            for(int j=0;j<16;j++){
                int rb = (wn*128 + j*8 + (l>>2))*SB_STR + kb + (l&3)*2;
                uint2 q0 = *(uint2*)(sB+rb), q1 = *(uint2*)(sB+rb+8);
                unsigned bh[2], bl[2];
                bh[0]=__byte_perm(q0.x,q0.y,0x5410); bl[0]=__byte_perm(q0.x,q0.y,0x7632);
                bh[1]=__byte_perm(q1.x,q1.y,0x5410); bl[1]=__byte_perm(q1.x,q1.y,0x7632);
#pragma unroll
                for(int t=0;t<2;t++){
                    mma16816(acc[t][j], ah[t], bh);
                    mma16816(acc[t][j], ah[t], bl);
                    mma16816(acc[t][j], al[t], bh);
                }
            }
        }
        __syncthreads();
    }
    // epilogue: direct fp32 stores (f0 is only 16.8 MB)
    float* f0p = g_f0 + ((size_t)g*C0C + m0)*HD;
#pragma unroll
    for(int t=0;t<2;t++)
#pragma unroll
        for(int j=0;j<16;j++){
            int col = wn*128 + j*8 + (l&3)*2;
            int r0 = wm*32 + t*16 + (l>>2);
            *(float2*)(f0p + (size_t)r0*HD + col)     = make_float2(acc[t][j][0],acc[t][j][1]);
            *(float2*)(f0p + (size_t)(r0+8)*HD + col) = make_float2(acc[t][j][2],acc[t][j][3]);
        }
}

// ---- k3: A1 = softmax(f0 @ W1 + b1) ----
__global__ __launch_bounds__(256) void k3_assign1(const float* __restrict__ W1, const float* __restrict__ b1){
    int gw = (blockIdx.x*blockDim.x + threadIdx.x)>>5;
    int lane = threadIdx.x&31;
    if (gw >= BG*C0C) return;
    const float* xr = g_f0 + (size_t)gw*HD;
    float a0=0.f, a1=0.f;
#pragma unroll 8
    for (int k=0;k<HD;k++){
        float xv = __ldg(xr+k);
        a0 = fmaf(xv, __ldg(W1+(size_t)k*C1C+lane), a0);
        a1 = fmaf(xv, __ldg(W1+(size_t)k*C1C+lane+32), a1);
    }
    a0 += __ldg(b1+lane); a1 += __ldg(b1+lane+32);
    float mx = fmaxf(a0,a1);
#pragma unroll
    for (int o=16;o;o>>=1) mx = fmaxf(mx, __shfl_xor_sync(~0u,mx,o));
    a0 = __expf(a0-mx); a1 = __expf(a1-mx);
    float s = a0+a1;
#pragma unroll
    for (int o=16;o;o>>=1) s += __shfl_xor_sync(~0u,s,o);
    float inv = 1.0f/s;
    g_A1[(size_t)gw*C1C+lane] = a0*inv;
    g_A1[(size_t)gw*C1C+lane+32] = a1*inv;
}

// ---- k4: f1 = A1^T @ f0 per graph ----
__global__ __launch_bounds__(256) void k4_pool1(){
    __shared__ float As[32][64];
    __shared__ float Fs[32][128];
    const int g = blockIdx.y, n0 = blockIdx.x*128;
    const int tid = threadIdx.x, tx = tid&15, ty = tid>>4;
    float acc[4][8];
#pragma unroll
    for (int i=0;i<4;i++)
#pragma unroll
        for (int j=0;j<8;j++) acc[i][j]=0.f;
    const float* A1p = g_A1 + (size_t)g*C0C*C1C;
    const float* f0p = g_f0 + (size_t)g*C0C*HD;
    for (int kb=0;kb<C0C;kb+=32){
#pragma unroll
        for (int i=0;i<2;i++){
            int idx = tid + i*256;
            *(float4*)&As[idx>>4][(idx&15)*4] = *(const float4*)(A1p + (size_t)(kb+(idx>>4))*C1C + (idx&15)*4);
        }
#pragma unroll
        for (int i=0;i<4;i++){
            int idx = tid + i*256;
            *(float4*)&Fs[idx>>5][(idx&31)*4] = *(const float4*)(f0p + (size_t)(kb+(idx>>5))*HD + n0 + (idx&31)*4);
        }
        __syncthreads();
#pragma unroll
        for (int k=0;k<32;k++){
            float a[4], b[8];
            *(float4*)&a[0] = *(float4*)&As[k][ty*4];
            *(float4*)&b[0] = *(float4*)&Fs[k][tx*4];
            *(float4*)&b[4] = *(float4*)&Fs[k][tx*4+64];
#pragma unroll
            for (int i=0;i<4;i++)
#pragma unroll
                for (int j=0;j<8;j++) acc[i][j] = fmaf(a[i], b[j], acc[i][j]);
        }
        __syncthreads();
    }
    float* f1p = g_f1 + (size_t)g*C1C*HD;
#pragma unroll
    for (int ii=0;ii<4;ii++)
#pragma unroll
        for (int gn=0;gn<2;gn++)
            *(float4*)(f1p + (size_t)(ty*4+ii)*HD + n0 + tx*4 + gn*64) =
                make_float4(acc[ii][gn*4],acc[ii][gn*4+1],acc[ii][gn*4+2],acc[ii][gn*4+3]);
}

// ---- k5: K-split final GEMM partials ----
__global__ __launch_bounds__(256) void k5_final_part(const float* __restrict__ Wf){
    __shared__ float Fs[64][33];
    __shared__ float Ws[32][32];
    const int n0 = blockIdx.x*32, ks = blockIdx.y;
    const int tid = threadIdx.x, tx = tid&31, ty = tid>>5;
    float acc[8];
#pragma unroll
    for (int i=0;i<8;i++) acc[i]=0.f;
    const int kbeg = ks*1024;
    for (int kb=kbeg; kb<kbeg+1024; kb+=32){
#pragma unroll
        for (int i=0;i<2;i++){
            int idx = tid + i*256;
            int m = idx>>3, k = (idx&7)*4;
            float4 v = *(const float4*)(g_f1 + (size_t)m*(C1C*HD) + kb + k);
            Fs[m][k]=v.x; Fs[m][k+1]=v.y; Fs[m][k+2]=v.z; Fs[m][k+3]=v.w;
        }
        *(float4*)&Ws[tid>>3][(tid&7)*4] = *(const float4*)(Wf + (size_t)(kb+(tid>>3))*HD + n0 + (tid&7)*4);
        __syncthreads();
#pragma unroll
        for (int kk=0;kk<32;kk++){
            float b = Ws[kk][tx];
#pragma unroll
            for (int i=0;i<8;i++) acc[i] = fmaf(Fs[ty*8+i][kk], b, acc[i]);
        }
        __syncthreads();
    }
#pragma unroll
    for (int i=0;i<8;i++)
        g_part[(size_t)(ks*BG + ty*8+i)*HD + n0 + tx] = acc[i];
}

// ---- k6: reduce + bias + relu ----
__global__ __launch_bounds__(256) void k6_reduce(const float* __restrict__ bf, float* __restrict__ out){
    int idx = blockIdx.x*256 + threadIdx.x;
    float s = __ldg(bf + (idx&255));
#pragma unroll
    for (int ks=0;ks<KSPLIT;ks++) s += g_part[(size_t)ks*(BG*HD) + idx];
    out[idx] = fmaxf(s, 0.f);
}

extern "C" void kernel_launch(void* const* d_in, const int* in_sizes, int n_in,
                              void* d_out, int out_size){
    const float* x  = (const float*)d_in[0];
    const float* W0 = (const float*)d_in[3];
    const float* b0 = (const float*)d_in[4];
    const float* W1 = (const float*)d_in[5];
    const float* b1 = (const float*)d_in[6];
    const float* Wf = (const float*)d_in[7];
    const float* bf = (const float*)d_in[8];
    float* out = (float*)d_out;

    cudaFuncSetAttribute(k1m, cudaFuncAttributeMaxDynamicSharedMemorySize, K1_SMEM);
    cudaFuncSetAttribute(k2m, cudaFuncAttributeMaxDynamicSharedMemorySize, K2_SMEM);

    kW<<<C0C*HD/256, 256>>>(W0);
    k1m<<<NTOT/128, 256, K1_SMEM>>>(x, b0);
    k2m<<<dim3(2, BG), 256, K2_SMEM>>>(x);
    k3_assign1<<<BG*C0C*32/256, 256>>>(W1, b1);
    k4_pool1<<<dim3(2, BG), 256>>>();
    k5_final_part<<<dim3(8, KSPLIT), 256>>>(Wf);
    k6_reduce<<<BG*HD/256, 256>>>(bf, out);
}